// round 11
// baseline (speedup 1.0000x reference)
#include <cuda_runtime.h>
#include <stdint.h>

#define N_ANCH   25200
#define NDIM     85
#define NCLS     80
#define TOPK     1000
#define NB_MAX   32
#define NBINS    4096
#define BCAP     16
#define CAND     2048              // rescue sort size (power of 2)
#define FLOORF   0.9375f           // capture floor; bins span [0.9375, 1)
#define BINSCALE 65536.0f          // 4096 / 0.0625
#define K1_THREADS 256
#define K1_MLP     2
#define BLK_ITEMS  (K1_THREADS * K1_MLP)                  // 512
#define NBLK       ((N_ANCH + BLK_ITEMS - 1) / BLK_ITEMS) // 50
#define ROWS_PER_CTA 25
#define K3BLK     (TOPK / ROWS_PER_CTA)                   // 40 CTAs per batch
#define K3_THREADS 256
#define BPT       (NBINS / K3_THREADS)                    // 16 bins per thread

__device__ unsigned int       g_hist[NB_MAX][NBINS];      // zero-init; k3 CTA0 re-zeroes
__device__ unsigned long long g_bucket[NB_MAX][NBINS * BCAP];
__device__ unsigned int       g_done[NB_MAX];             // zero-init; k3 CTA0 resets

// ---------------- K1: pure scan; capture only items >= FLOORF ----------------
__global__ __launch_bounds__(K1_THREADS) void k1_scan(const float* __restrict__ pred) {
    const int b  = blockIdx.y;
    const int i0 = blockIdx.x * BLK_ITEMS;
    const float* base = pred + (size_t)b * N_ANCH * NDIM;

    float v[K1_MLP];
    int   idx[K1_MLP];
#pragma unroll
    for (int s = 0; s < K1_MLP; s++) {       // batch the loads
        idx[s] = i0 + s * K1_THREADS + threadIdx.x;
        v[s] = (idx[s] < N_ANCH) ? __ldcg(base + (size_t)idx[s] * NDIM + 4) : 0.0f;
    }
#pragma unroll
    for (int s = 0; s < K1_MLP; s++) {
        float f = v[s];
        if (idx[s] >= N_ANCH || !(f >= FLOORF)) continue;   // ~97% exit here
        int bin = (int)((f - FLOORF) * BINSCALE);
        bin = min(max(bin, 0), NBINS - 1);
        unsigned int pos = atomicAdd(&g_hist[b][bin], 1u);
        if (pos < BCAP)
            g_bucket[b][bin * BCAP + pos] =
                ((unsigned long long)__float_as_uint(f) << 32) |
                (unsigned int)(~(unsigned int)idx[s]);
    }
#if __CUDA_ARCH__ >= 900
    cudaTriggerProgrammaticLaunchCompletion();   // release k3 as CTAs drain
#endif
}

// ============ K3: redundant select (per CTA) + gather + emit, 2-kernel pipeline ============
// grid (K3BLK, B): each CTA rebuilds the sorted top-1000 in smem from hist/buckets
// (cheap, L2-resident), then emits its own 25 rows. CTA 0 of each batch re-zeroes
// hist after all batch peers have signalled they are done reading it.
__global__ __launch_bounds__(K3_THREADS) void k3_select_emit(
        const float* __restrict__ pred,
        float* __restrict__ scores_out,
        float* __restrict__ boxes_out) {
    __shared__ unsigned long long s_keys[CAND];   // [0..TOPK) = sorted top-K; full for rescue
    __shared__ unsigned int s_suf[K3_THREADS];
    __shared__ unsigned int s_wsum[8], s_wsuf[8];
    __shared__ int s_tbin, s_pos, s_flag;
    __shared__ unsigned int s_hist256[256];
    __shared__ unsigned int s_sel, s_k;

    const int b = blockIdx.y, tid = threadIdx.x, lane = tid & 31, w = tid >> 5;

#if __CUDA_ARCH__ >= 900
    cudaGridDependencySynchronize();    // PDL: wait for k1's writes before reading
#endif

    // ---- load my 16 bins (4x uint4); signal "hist read" for the zeroer ----
    unsigned int loc[BPT];
    {
        const uint4* hp = (const uint4*)g_hist[b];
#pragma unroll
        for (int j = 0; j < BPT / 4; j++) {
            uint4 h4 = hp[tid * (BPT / 4) + j];
            loc[j * 4 + 0] = h4.x; loc[j * 4 + 1] = h4.y;
            loc[j * 4 + 2] = h4.z; loc[j * 4 + 3] = h4.w;
        }
    }
    __syncthreads();                     // all threads' hist loads issued+consumed
    if (tid == 0) {
        __threadfence();                 // order: my CTA's reads precede the signal
        atomicAdd(&g_done[b], 1u);
    }

    unsigned int tot = 0;
#pragma unroll
    for (int i = 0; i < BPT; i++) tot += loc[i];

    // ---- suffix scan over 256 thread sums (shuffles, 8 warps) ----
    unsigned int vsc = tot;
#pragma unroll
    for (int off = 1; off < 32; off <<= 1) {
        unsigned int t = __shfl_down_sync(0xffffffffu, vsc, off);
        if (lane + off < 32) vsc += t;
    }
    if (lane == 0) s_wsum[w] = vsc;
    if (tid == 0) { s_pos = 0; s_flag = 0; }
    __syncthreads();
    if (w == 0) {
        unsigned int wv = (lane < 8) ? s_wsum[lane] : 0u;
#pragma unroll
        for (int off = 1; off < 8; off <<= 1) {
            unsigned int t = __shfl_down_sync(0xffffffffu, wv, off);
            if (lane + off < 8) wv += t;
        }
        if (lane < 8) s_wsuf[lane] = wv;
    }
    __syncthreads();
    const unsigned int mysuf = vsc + ((w < 7) ? s_wsuf[w + 1] : 0u);
    s_suf[tid] = mysuf;
    __syncthreads();
    const unsigned int total = s_wsuf[0];        // items >= FLOORF

    if (total >= TOPK) {
        unsigned int S = mysuf;
#pragma unroll
        for (int i = 0; i < BPT; i++) {
            if (S >= TOPK && S - loc[i] < TOPK)      // unique crossing bin
                s_tbin = tid * BPT + i;
            S -= loc[i];
        }
    } else if (tid == 0) s_flag = 1;
    __syncthreads();
    const int tbin = s_tbin;

    bool ovf = false;
#pragma unroll
    for (int i = 0; i < BPT; i++)
        ovf |= (tid * BPT + i >= tbin) && (loc[i] > BCAP);
    if (__syncthreads_or(ovf)) { if (tid == 0) s_flag = 1; }
    __syncthreads();

    if (!s_flag) {
        // ---- fast path: in-bin ranks -> sorted top-K in s_keys ----
        unsigned int acc = (tid < K3_THREADS - 1) ? s_suf[tid + 1] : 0u;
        unsigned int gt[BPT];
#pragma unroll
        for (int i = BPT - 1; i >= 0; i--) { gt[i] = acc; acc += loc[i]; }

#pragma unroll
        for (int i = 0; i < BPT; i++) {
            const int bin = tid * BPT + i;
            const int c = (int)loc[i];
            if (bin < tbin || c == 0 || gt[i] >= TOPK) continue;
            unsigned long long kk[BCAP];
            for (int j = 0; j < c; j++) kk[j] = g_bucket[b][bin * BCAP + j];
            for (int j = 0; j < c; j++) {        // in-bin rank: (value desc, idx asc)
                int r = (int)gt[i];
                for (int m = 0; m < c; m++) r += (kk[m] > kk[j]);
                if (r < TOPK) s_keys[r] = kk[j];
            }
        }
        __syncthreads();
    } else {
        // ---- rescue: redundant exact radix select + bitonic sort (never on this data) ----
        const float* base = pred + (size_t)b * N_ANCH * NDIM;
        if (tid == 0) s_k = TOPK;
        __syncthreads();
        unsigned int prefix = 0, prefmask = 0;
        for (int pass = 0; pass < 4; pass++) {
            const int shift = 24 - 8 * pass;
            s_hist256[tid] = 0;
            __syncthreads();
            for (int i = tid; i < N_ANCH; i += K3_THREADS) {
                unsigned int bits = __float_as_uint(__ldcg(base + (size_t)i * NDIM + 4));
                bool ok = ((bits & prefmask) == prefix);
                unsigned int digit = ok ? ((bits >> shift) & 255u) : 0xffffffffu;
                unsigned int m = __match_any_sync(0xffffffffu, digit);
                if (ok && lane == (__ffs(m) - 1))
                    atomicAdd(&s_hist256[digit], (unsigned int)__popc(m));
            }
            __syncthreads();
            unsigned int kcur = s_k;
            __syncthreads();
            for (int off = 1; off < 256; off <<= 1) {
                unsigned int t = (tid + off < 256) ? s_hist256[tid + off] : 0u;
                __syncthreads();
                s_hist256[tid] += t;
                __syncthreads();
            }
            {
                unsigned int ge = s_hist256[tid];
                unsigned int gtv = (tid == 255) ? 0u : s_hist256[tid + 1];
                if (ge >= kcur && gtv < kcur) { s_sel = (unsigned int)tid; s_k = kcur - gtv; }
            }
            __syncthreads();
            prefix   |= s_sel << shift;
            prefmask |= 255u << shift;
            __syncthreads();
        }
        for (int i = tid; i < N_ANCH; i += K3_THREADS) {
            unsigned int bits = __float_as_uint(__ldcg(base + (size_t)i * NDIM + 4));
            if (bits >= prefix) {
                int p = atomicAdd(&s_pos, 1);
                if (p < CAND)
                    s_keys[p] = ((unsigned long long)bits << 32) |
                                (unsigned int)(~(unsigned int)i);
            }
        }
        __syncthreads();
        int cnt = min(s_pos, CAND);
        for (int i = tid; i < CAND; i += K3_THREADS)
            if (i >= cnt) s_keys[i] = 0ull;          // padding sorts last
        __syncthreads();
        for (int ksz = 2; ksz <= CAND; ksz <<= 1) {  // bitonic sort, descending
            for (int j = ksz >> 1; j > 0; j >>= 1) {
                for (int t = tid; t < CAND; t += K3_THREADS) {
                    int l = t ^ j;
                    if (l > t) {
                        unsigned long long a = s_keys[t], c2 = s_keys[l];
                        bool sw = ((t & ksz) == 0) ? (a < c2) : (a > c2);
                        if (sw) { s_keys[t] = c2; s_keys[l] = a; }
                    }
                }
                __syncthreads();
            }
        }
    }

    // ---- emit this CTA's 25 rows (warp w owns rows rbase + w + 8j) ----
    {
        const int rbase = blockIdx.x * ROWS_PER_CTA;
        const float* batch = pred + (size_t)b * N_ANCH * NDIM;
        const int nrows = (ROWS_PER_CTA - w + 7) >> 3;     // 4 for w=0, else 3

        float cls[4][3], bxy[4], bwh[4], validv[4];
        int   rowidx[4];
#pragma unroll
        for (int j = 0; j < 4; j++) {
            if (j >= nrows) break;                         // warp-uniform
            const int r = rbase + w + 8 * j;
            const unsigned long long key = s_keys[r];      // smem broadcast
            const int idx = (int)(~(unsigned int)key);
            const float val = __uint_as_float((unsigned int)(key >> 32));
            validv[j] = (val > 0.25f) ? val : 0.0f;
            rowidx[j] = r;
            const float* row = batch + (size_t)idx * NDIM;
#pragma unroll
            for (int k = 0; k < 3; k++) {
                int c = lane + 32 * k;
                cls[j][k] = (c < NCLS) ? row[5 + c] : 0.0f;
            }
            if (lane < 4) {
                bxy[j] = row[lane & 1];
                bwh[j] = row[2 + (lane & 1)];
            }
        }
#pragma unroll
        for (int j = 0; j < 4; j++) {
            if (j >= nrows) break;
            const int r = rowidx[j];
            float* srow = scores_out + ((size_t)b * TOPK + r) * NCLS;
#pragma unroll
            for (int k = 0; k < 3; k++) {
                int c = lane + 32 * k;
                if (c < NCLS) {
                    float m = cls[j][k] * validv[j];
                    srow[c] = (m > 0.25f) ? m : 0.0f;
                }
            }
            if (lane < 4) {                                // xywh -> xyxy
                float half = bwh[j] * 0.5f;
                float o = (lane < 2) ? (bxy[j] - half) : (bxy[j] + half);
                boxes_out[((size_t)b * TOPK + r) * 4 + lane] = o;
            }
        }
    }

    // ---- CTA 0 of each batch: wait for peers, then re-zero hist for next replay ----
    if (blockIdx.x == 0) {
        __syncthreads();
        if (tid == 0) {
            while (atomicAdd(&g_done[b], 0u) < K3BLK)
                __nanosleep(100);
            __threadfence();
        }
        __syncthreads();
        uint4* hp = (uint4*)g_hist[b];
#pragma unroll
        for (int j = 0; j < BPT / 4; j++)
            hp[tid * (BPT / 4) + j] = make_uint4(0, 0, 0, 0);
        __syncthreads();
        if (tid == 0) {
            __threadfence();
            atomicExch(&g_done[b], 0u);   // reset for next replay
        }
    }
}

extern "C" void kernel_launch(void* const* d_in, const int* in_sizes, int n_in,
                              void* d_out, int out_size) {
    const float* pred = (const float*)d_in[0];
    const int B = in_sizes[0] / (N_ANCH * NDIM);

    float* scores = (float*)d_out;                       // (B, TOPK, NCLS)
    float* boxes  = scores + (size_t)B * TOPK * NCLS;    // (B, TOPK, 4)

    k1_scan<<<dim3(NBLK, B), K1_THREADS>>>(pred);

    cudaLaunchAttribute attr[1];
    attr[0].id = cudaLaunchAttributeProgrammaticStreamSerialization;
    attr[0].val.programmaticStreamSerializationAllowed = 1;

    cudaLaunchConfig_t cfg = {};
    cfg.gridDim  = dim3(K3BLK, B, 1);
    cfg.blockDim = dim3(K3_THREADS, 1, 1);
    cfg.attrs = attr;
    cfg.numAttrs = 1;
    cudaLaunchKernelEx(&cfg, k3_select_emit, pred, scores, boxes);
}

// round 12
// speedup vs baseline: 2.1685x; 2.1685x over previous
#include <cuda_runtime.h>
#include <stdint.h>

#define N_ANCH   25200
#define NDIM     85
#define NCLS     80
#define TOPK     1000
#define NB_MAX   32
#define NBINS    4096
#define BCAP     16
#define CAND     2048              // rescue sort size (power of 2)
#define FLOORF   0.9375f           // capture floor; bins span [0.9375, 1)
#define BINSCALE 65536.0f          // 4096 / 0.0625
#define K1_THREADS 256
#define K1_MLP     2
#define BLK_ITEMS  (K1_THREADS * K1_MLP)                  // 512
#define NBLK       ((N_ANCH + BLK_ITEMS - 1) / BLK_ITEMS) // 50
#define NPT        25              // rescue: ceil(25200/1024)
#define ROWS_PER_CTA 25
#define K3BLK     (TOPK / ROWS_PER_CTA)                   // 40

__device__ unsigned int       g_hist[NB_MAX][NBINS];      // zero-init; k2 re-zeroes
__device__ unsigned long long g_bucket[NB_MAX][NBINS * BCAP];
__device__ unsigned long long g_cand[NB_MAX][TOPK];       // rank-ordered keys
__device__ unsigned int       g_done[NB_MAX];             // k1 CTAs done per batch
__device__ unsigned int       g_candready[NB_MAX];        // k2 -> k3 flag
__device__ unsigned int       g_seen[NB_MAX];             // k3 CTAs that consumed flag

// ---------------- K1: pure scan; capture only items >= FLOORF; per-batch release ----------------
__global__ __launch_bounds__(K1_THREADS) void k1_scan(const float* __restrict__ pred) {
#if __CUDA_ARCH__ >= 900
    cudaTriggerProgrammaticLaunchCompletion();   // EARLY: let k2 launch + spin
#endif
    const int b  = blockIdx.y;
    const int i0 = blockIdx.x * BLK_ITEMS;
    const float* base = pred + (size_t)b * N_ANCH * NDIM;

    float v[K1_MLP];
    int   idx[K1_MLP];
#pragma unroll
    for (int s = 0; s < K1_MLP; s++) {       // batch the loads
        idx[s] = i0 + s * K1_THREADS + threadIdx.x;
        v[s] = (idx[s] < N_ANCH) ? __ldcg(base + (size_t)idx[s] * NDIM + 4) : 0.0f;
    }
#pragma unroll
    for (int s = 0; s < K1_MLP; s++) {
        float f = v[s];
        if (idx[s] >= N_ANCH || !(f >= FLOORF)) continue;   // ~97% exit here
        int bin = (int)((f - FLOORF) * BINSCALE);
        bin = min(max(bin, 0), NBINS - 1);
        unsigned int pos = atomicAdd(&g_hist[b][bin], 1u);
        if (pos < BCAP)
            g_bucket[b][bin * BCAP + pos] =
                ((unsigned long long)__float_as_uint(f) << 32) |
                (unsigned int)(~(unsigned int)idx[s]);
    }
    // release: publish this CTA's hist/bucket writes, then count in
    __threadfence();
    __syncthreads();
    if (threadIdx.x == 0) atomicAdd(&g_done[b], 1u);
}

// ---------------- K2: per-batch spin -> exact rank -> g_cand[rank]; release flag ----------------
__global__ __launch_bounds__(1024) void k2_select(const float* __restrict__ pred) {
    __shared__ unsigned int s_suf[1024];
    __shared__ unsigned int s_wsum[32], s_wsuf[32];
    __shared__ int s_tbin, s_pos, s_flag;
    __shared__ unsigned int s_hist256[256];
    __shared__ unsigned int s_sel, s_k;
    __shared__ unsigned long long s_keys[CAND];   // rescue only

    const int b = blockIdx.x, tid = threadIdx.x, lane = tid & 31, w = tid >> 5;

#if __CUDA_ARCH__ >= 900
    cudaTriggerProgrammaticLaunchCompletion();   // EARLY: let k3 launch + spin
#endif

    // acquire: wait until all NBLK k1 CTAs of my batch have published
    if (tid == 0)
        while (*((volatile unsigned int*)&g_done[b]) < NBLK) __nanosleep(100);
    __syncthreads();
    __threadfence();

    // load my 4 contiguous bins (vectorized), then immediately re-zero them
    uint4 h4 = ((uint4*)g_hist[b])[tid];
    ((uint4*)g_hist[b])[tid] = make_uint4(0, 0, 0, 0);
    unsigned int loc[4] = {h4.x, h4.y, h4.z, h4.w};
    unsigned int tot = loc[0] + loc[1] + loc[2] + loc[3];

    // ---- suffix scan via shuffles ----
    unsigned int vsc = tot;
#pragma unroll
    for (int off = 1; off < 32; off <<= 1) {
        unsigned int t = __shfl_down_sync(0xffffffffu, vsc, off);
        if (lane + off < 32) vsc += t;
    }
    if (lane == 0) s_wsum[w] = vsc;
    if (tid == 0) { s_pos = 0; s_flag = 0; g_done[b] = 0; }   // reset for next replay
    __syncthreads();
    if (w == 0) {
        unsigned int wv = s_wsum[lane];
#pragma unroll
        for (int off = 1; off < 32; off <<= 1) {
            unsigned int t = __shfl_down_sync(0xffffffffu, wv, off);
            if (lane + off < 32) wv += t;
        }
        s_wsuf[lane] = wv;
    }
    __syncthreads();
    s_suf[tid] = vsc + ((w < 31) ? s_wsuf[w + 1] : 0u);
    __syncthreads();
    const unsigned int total = s_suf[0];         // items >= FLOORF

    if (total >= TOPK) {
        unsigned int S = s_suf[tid];
#pragma unroll
        for (int i = 0; i < 4; i++) {
            if (S >= TOPK && S - loc[i] < TOPK)      // unique crossing bin
                s_tbin = tid * 4 + i;
            S -= loc[i];
        }
    } else if (tid == 0) s_flag = 1;
    __syncthreads();
    const int tbin = s_tbin;

    bool ovf = false;
#pragma unroll
    for (int i = 0; i < 4; i++)
        ovf |= (tid * 4 + i >= tbin) && (loc[i] > BCAP);
    if (__syncthreads_or(ovf)) { if (tid == 0) s_flag = 1; }
    __syncthreads();

    if (!s_flag) {
        // ---- fast path: in-bin ranks -> g_cand[rank] ----
        unsigned int acc = (tid < 1023) ? s_suf[tid + 1] : 0u;
        unsigned int gt[4];
#pragma unroll
        for (int i = 3; i >= 0; i--) { gt[i] = acc; acc += loc[i]; }

#pragma unroll
        for (int i = 0; i < 4; i++) {
            const int bin = tid * 4 + i;
            const int c = (int)loc[i];
            if (bin < tbin || c == 0 || gt[i] >= TOPK) continue;
            unsigned long long kk[BCAP];
            for (int j = 0; j < c; j++) kk[j] = g_bucket[b][bin * BCAP + j];
            for (int j = 0; j < c; j++) {        // in-bin rank: (value desc, idx asc)
                int r = (int)gt[i];
                for (int m = 0; m < c; m++) r += (kk[m] > kk[j]);
                if (r < TOPK) g_cand[b][r] = kk[j];
            }
        }
    } else {
        // ---- rescue: exact radix select + bitonic sort (never on this data) ----
        const float* base = pred + (size_t)b * N_ANCH * NDIM;
        unsigned int rv[NPT];
#pragma unroll
        for (int s = 0; s < NPT; s++) {
            int i = s * 1024 + tid;
            rv[s] = (i < N_ANCH)
                  ? __float_as_uint(__ldcg(base + (size_t)i * NDIM + 4)) : 0u;
        }
        if (tid == 0) s_k = TOPK;
        __syncthreads();
        unsigned int prefix = 0, prefmask = 0;
        for (int pass = 0; pass < 4; pass++) {
            const int shift = 24 - 8 * pass;
            if (tid < 256) s_hist256[tid] = 0;
            __syncthreads();
#pragma unroll
            for (int s = 0; s < NPT; s++) {
                int i = s * 1024 + tid;
                bool ok = (i < N_ANCH) && ((rv[s] & prefmask) == prefix);
                unsigned int digit = ok ? ((rv[s] >> shift) & 255u) : 0xffffffffu;
                unsigned int m = __match_any_sync(0xffffffffu, digit);
                if (ok && lane == (__ffs(m) - 1))
                    atomicAdd(&s_hist256[digit], (unsigned int)__popc(m));
            }
            __syncthreads();
            unsigned int kcur = s_k;
            __syncthreads();
            for (int off = 1; off < 256; off <<= 1) {
                unsigned int t = 0;
                if (tid < 256 && tid + off < 256) t = s_hist256[tid + off];
                __syncthreads();
                if (tid < 256) s_hist256[tid] += t;
                __syncthreads();
            }
            if (tid < 256) {
                unsigned int ge = s_hist256[tid];
                unsigned int gtv = (tid == 255) ? 0u : s_hist256[tid + 1];
                if (ge >= kcur && gtv < kcur) { s_sel = (unsigned int)tid; s_k = kcur - gtv; }
            }
            __syncthreads();
            prefix   |= s_sel << shift;
            prefmask |= 255u << shift;
            __syncthreads();
        }
#pragma unroll
        for (int s = 0; s < NPT; s++) {
            int i = s * 1024 + tid;
            if (i < N_ANCH && rv[s] >= prefix) {
                int p = atomicAdd(&s_pos, 1);
                if (p < CAND)
                    s_keys[p] = ((unsigned long long)rv[s] << 32) |
                                (unsigned int)(~(unsigned int)i);
            }
        }
        __syncthreads();
        int cnt = min(s_pos, CAND);
        for (int i = tid; i < CAND; i += 1024)
            if (i >= cnt) s_keys[i] = 0ull;          // padding sorts last
        __syncthreads();
        for (int ksz = 2; ksz <= CAND; ksz <<= 1) {  // bitonic sort, descending
            for (int j = ksz >> 1; j > 0; j >>= 1) {
                for (int t = tid; t < CAND; t += 1024) {
                    int l = t ^ j;
                    if (l > t) {
                        unsigned long long a = s_keys[t], c2 = s_keys[l];
                        bool sw = ((t & ksz) == 0) ? (a < c2) : (a > c2);
                        if (sw) { s_keys[t] = c2; s_keys[l] = a; }
                    }
                }
                __syncthreads();
            }
        }
        if (tid < TOPK) g_cand[b][tid] = s_keys[tid];
        if (tid + 1024 < TOPK) g_cand[b][tid + 1024] = s_keys[tid + 1024];
    }

    // release: publish g_cand, then raise the per-batch flag
    __threadfence();
    __syncthreads();
    if (tid == 0) atomicExch(&g_candready[b], 1u);
}

// ---------------- K3: per-batch spin -> gather + emit (4 rows per warp) ----------------
__global__ __launch_bounds__(256) void k3_emit(const float* __restrict__ pred,
                                               float* __restrict__ scores_out,
                                               float* __restrict__ boxes_out) {
    const int b = blockIdx.y;
    const int w = threadIdx.x >> 5, lane = threadIdx.x & 31;
    const int base = blockIdx.x * ROWS_PER_CTA;

    // acquire: wait until k2 published this batch's sorted keys
    if (threadIdx.x == 0)
        while (*((volatile unsigned int*)&g_candready[b]) == 0u) __nanosleep(100);
    __syncthreads();
    __threadfence();

    // phase 1: prefetch this warp's keys (lane j<4 loads key for row base+w+8j)
    unsigned long long mykey = 0ull;
    if (lane < 4) {
        int rr = base + w + 8 * lane;
        if (w + 8 * lane < ROWS_PER_CTA && rr < TOPK)
            mykey = g_cand[b][rr];
    }

    const float* batch = pred + (size_t)b * N_ANCH * NDIM;
    const int nrows = (ROWS_PER_CTA - w + 7) >> 3;     // 4 for w=0, else 3

    // phase 2: issue ALL gather loads into registers (high MLP)
    float cls[4][3], bxy[4], bwh[4], validv[4];
    int   rowidx[4];
#pragma unroll
    for (int j = 0; j < 4; j++) {
        if (j >= nrows) break;                         // warp-uniform
        unsigned long long key = __shfl_sync(0xffffffffu, mykey, j);
        const int idx = (int)(~(unsigned int)key);
        const float val = __uint_as_float((unsigned int)(key >> 32));
        validv[j] = (val > 0.25f) ? val : 0.0f;
        rowidx[j] = base + w + 8 * j;
        const float* row = batch + (size_t)idx * NDIM;
#pragma unroll
        for (int k = 0; k < 3; k++) {
            int c = lane + 32 * k;
            cls[j][k] = (c < NCLS) ? row[5 + c] : 0.0f;
        }
        if (lane < 4) {
            bxy[j] = row[lane & 1];
            bwh[j] = row[2 + (lane & 1)];
        }
    }

    // phase 3: coalesced stores
#pragma unroll
    for (int j = 0; j < 4; j++) {
        if (j >= nrows) break;
        const int r = rowidx[j];
        float* srow = scores_out + ((size_t)b * TOPK + r) * NCLS;
#pragma unroll
        for (int k = 0; k < 3; k++) {
            int c = lane + 32 * k;
            if (c < NCLS) {
                float m = cls[j][k] * validv[j];
                srow[c] = (m > 0.25f) ? m : 0.0f;
            }
        }
        if (lane < 4) {                                // xywh -> xyxy
            float half = bwh[j] * 0.5f;
            float o = (lane < 2) ? (bxy[j] - half) : (bxy[j] + half);
            boxes_out[((size_t)b * TOPK + r) * 4 + lane] = o;
        }
    }

    // replay hygiene: last consumer of this batch resets the flag + counter
    __syncthreads();
    if (threadIdx.x == 0) {
        unsigned int v = atomicAdd(&g_seen[b], 1u);
        if (v == K3BLK - 1) {          // all 40 CTAs have passed the spin
            g_candready[b] = 0u;
            g_seen[b] = 0u;
            __threadfence();
        }
    }
}

extern "C" void kernel_launch(void* const* d_in, const int* in_sizes, int n_in,
                              void* d_out, int out_size) {
    const float* pred = (const float*)d_in[0];
    const int B = in_sizes[0] / (N_ANCH * NDIM);

    float* scores = (float*)d_out;                       // (B, TOPK, NCLS)
    float* boxes  = scores + (size_t)B * TOPK * NCLS;    // (B, TOPK, 4)

    k1_scan<<<dim3(NBLK, B), K1_THREADS>>>(pred);

    cudaLaunchAttribute attr[1];
    attr[0].id = cudaLaunchAttributeProgrammaticStreamSerialization;
    attr[0].val.programmaticStreamSerializationAllowed = 1;

    {   // k2 launches while k1 runs (k1 triggers at start); spins per batch
        cudaLaunchConfig_t cfg = {};
        cfg.gridDim  = dim3(B, 1, 1);
        cfg.blockDim = dim3(1024, 1, 1);
        cfg.attrs = attr;
        cfg.numAttrs = 1;
        cudaLaunchKernelEx(&cfg, k2_select, pred);
    }
    {   // k3 launches while k2 runs (k2 triggers at start); spins per batch
        cudaLaunchConfig_t cfg = {};
        cfg.gridDim  = dim3(K3BLK, B, 1);
        cfg.blockDim = dim3(256, 1, 1);
        cfg.attrs = attr;
        cfg.numAttrs = 1;
        cudaLaunchKernelEx(&cfg, k3_emit, pred, scores, boxes);
    }
}